// round 7
// baseline (speedup 1.0000x reference)
#include <cuda_runtime.h>
#include <cstddef>

// Problem constants
#define BB    4096
#define NXD   64
#define NUD   16
#define HH    50
#define HIDD  256
#define ZD    80
#define W1STRIDE 260    // floats; 16B-aligned rows, stride%32==4 -> conflict-free LDS.128
#define W2STRIDE 260

// Output layout
#define OFF_U      0
#define OFF_XTRAJ  (BB*NUD)
#define OFF_XPRED  (OFF_XTRAJ + BB*(HH+1)*NXD)
#define OFF_GX     (OFF_XPRED + BB*HH*NXD)
#define OFF_GU     (OFF_GX + BB*HH*NXD)

#define NWARP 4     // warps per CTA
#define RPW   8     // batch rows per warp

typedef unsigned long long ull;

__device__ float g_u9[BB * HH * NUD];

union F2U { ull u; float2 f; };

__device__ __forceinline__ ull fma2(ull a, ull b, ull c) {
    ull d;
    asm("fma.rn.f32x2 %0, %1, %2, %3;" : "=l"(d) : "l"(a), "l"(b), "l"(c));
    return d;
}
__device__ __forceinline__ ull mul2(ull a, ull b) {
    ull d;
    asm("mul.rn.f32x2 %0, %1, %2;" : "=l"(d) : "l"(a), "l"(b));
    return d;
}
// tanh(x) = 1 - 2/(exp2(2*log2e*x)+1): 2 MUFU + 3 fma-class ops, err ~1e-6
__device__ __forceinline__ float tanhfast(float x) {
    float e, r;
    asm("ex2.approx.f32 %0, %1;" : "=f"(e) : "f"(x * 2.885390081777927f));
    asm("rcp.approx.f32 %0, %1;" : "=f"(r) : "f"(e + 1.0f));
    return fmaf(-2.0f, r, 1.0f);
}

// ---------------------------------------------------------------------------
__global__ void prep_kernel(const float* __restrict__ noise,
                            const int* __restrict__ nit_p,
                            float* __restrict__ out_u) {
    const int TOT = BB * HH * NUD;
    int idx = blockIdx.x * blockDim.x + threadIdx.x;
    if (idx >= TOT) return;
    int nit = *nit_p;
    float s = 0.f;
    for (int it = 0; it < nit - 1; ++it)
        s += noise[(size_t)it * TOT + idx];
    float u9 = 0.001f * s;
    g_u9[idx] = u9;
    int rem = idx % (HH * NUD);
    if (rem < NUD) {
        float u10 = u9 + 0.001f * noise[(size_t)(nit - 1) * TOT + idx];
        int b = idx / (HH * NUD);
        out_u[b * NUD + rem] = u10;
    }
}

// ---------------------------------------------------------------------------
// grid = 128 CTAs x 128 threads (4 warps); each warp carries 8 batch rows.
// Weight smem traffic amortized over 8 rows; packed fma.rn.f32x2 throughout.
// ---------------------------------------------------------------------------
__global__ __launch_bounds__(128, 1)
void mpc_kernel(const float* __restrict__ x0,
                const float* __restrict__ W1g,   // [80,256]
                const float* __restrict__ b1g,   // [256]
                const float* __restrict__ W2g,   // [256,64]
                float* __restrict__ out_xtraj,
                float* __restrict__ out_xpred,
                float* __restrict__ out_gx,
                float* __restrict__ out_gu) {
    extern __shared__ float smem[];
    float*  W1s  = smem;                              // [80][260]
    float*  W2Ts = W1s + ZD * W1STRIDE;               // [64][260] : W2Ts[c][m]=W2[m][c]
    float*  c2s  = W2Ts + NXD * W2STRIDE;             // [256]
    float*  b1s  = c2s + HIDD;                        // [256]
    float2* zdup = (float2*)(b1s + HIDD);             // [4 warps][8 rows][80] dup z
    float*  tall = (float*)(zdup + NWARP * RPW * ZD); // [4 warps][8 rows][256] t/gh

    const int tid = threadIdx.x;

    // ---- Stage weights ----
    for (int idx = tid; idx < ZD * HIDD; idx += 128) {
        int i = idx >> 8, m = idx & 255;
        W1s[i * W1STRIDE + m] = W1g[idx];
    }
    for (int idx = tid; idx < HIDD * NXD; idx += 128) {
        int m = idx >> 6, j = idx & 63;
        W2Ts[j * W2STRIDE + m] = W2g[idx];
    }
    for (int m = tid; m < HIDD; m += 128) {
        float s = 0.f;
        #pragma unroll 8
        for (int j = 0; j < NXD; ++j) s += W2g[m * NXD + j];
        c2s[m] = 0.1f * s;
        b1s[m] = b1g[m];
    }
    __syncthreads();

    const int w = tid >> 5, lane = tid & 31;
    float2* zd = zdup + w * RPW * ZD;      // per-warp [8][80]
    float*  tw = tall + w * RPW * HIDD;    // per-warp [8][256]
    const int b0 = blockIdx.x * 32 + w * RPW;
    const int m2 = 2 * lane;               // lane owns m-pairs {m2+64j : j=0..3}
    const bool lo = lane < 16;

    ull b1p[4], c2p[4], nc2p[4];
    #pragma unroll
    for (int j = 0; j < 4; ++j) {
        b1p[j] = *(const ull*)&b1s[64 * j + m2];
        F2U c; c.u = *(const ull*)&c2s[64 * j + m2];
        c2p[j] = c.u;
        F2U n; n.f.x = -c.f.x; n.f.y = -c.f.y;
        nc2p[j] = n.u;
    }

    // ---- Init state + x_traj[:,0,:] ----
    #pragma unroll
    for (int r = 0; r < RPW; ++r) {
        int b = b0 + r;
        float xa = x0[b * NXD + lane];
        float xb = x0[b * NXD + 32 + lane];
        zd[r * ZD + lane]      = make_float2(xa, xa);
        zd[r * ZD + 32 + lane] = make_float2(xb, xb);
        size_t base = (size_t)b * (HH + 1) * NXD;
        out_xtraj[base + lane]      = xa;
        out_xtraj[base + 32 + lane] = xb;
    }

    // u prefetch: per lane 4 of the 128 per-step controls
    const int urh = lane >> 4, ui = lane & 15;
    float up[4];
    #pragma unroll
    for (int v = 0; v < 4; ++v)
        up[v] = g_u9[(size_t)(b0 + 2 * v + urh) * HH * NUD + ui];

    const ulonglong2* w2a = (const ulonglong2*)&W2Ts[lane * W2STRIDE];
    const ulonglong2* w2b = (const ulonglong2*)&W2Ts[(lane + 32) * W2STRIDE];
    const ulonglong2* wia = (const ulonglong2*)&W1s[lane * W1STRIDE];
    const ulonglong2* wib = (const ulonglong2*)&W1s[(32 + lane) * W1STRIDE];
    const ulonglong2* wic = (const ulonglong2*)&W1s[(64 + ui) * W1STRIDE];

    for (int k = 0; k < HH; ++k) {
        // ---- stage controls (duplicated) ----
        #pragma unroll
        for (int v = 0; v < 4; ++v)
            zd[(2 * v + urh) * ZD + NXD + ui] = make_float2(up[v], up[v]);
        __syncwarp();
        if (k + 1 < HH) {
            #pragma unroll
            for (int v = 0; v < 4; ++v)
                up[v] = g_u9[(size_t)(b0 + 2 * v + urh) * HH * NUD
                             + (k + 1) * NUD + ui];
        }

        // ---- GEMV1: h = z @ W1 + b1 ----
        ull h[RPW][4];
        #pragma unroll
        for (int r = 0; r < RPW; ++r)
            #pragma unroll
            for (int j = 0; j < 4; ++j) h[r][j] = b1p[j];

        #pragma unroll 2
        for (int i = 0; i < ZD; i += 2) {
            const float* wr0 = &W1s[i * W1STRIDE];
            const float* wr1 = &W1s[(i + 1) * W1STRIDE];
            ull a0 = *(const ull*)&wr0[m2];
            ull a1 = *(const ull*)&wr0[m2 + 64];
            ull a2 = *(const ull*)&wr0[m2 + 128];
            ull a3 = *(const ull*)&wr0[m2 + 192];
            ull c0 = *(const ull*)&wr1[m2];
            ull c1 = *(const ull*)&wr1[m2 + 64];
            ull c2_ = *(const ull*)&wr1[m2 + 128];
            ull c3 = *(const ull*)&wr1[m2 + 192];
            #pragma unroll
            for (int r = 0; r < RPW; ++r) {
                ulonglong2 z2 = *(const ulonglong2*)&zd[r * ZD + i];
                h[r][0] = fma2(z2.x, a0, h[r][0]);
                h[r][1] = fma2(z2.x, a1, h[r][1]);
                h[r][2] = fma2(z2.x, a2, h[r][2]);
                h[r][3] = fma2(z2.x, a3, h[r][3]);
                h[r][0] = fma2(z2.y, c0, h[r][0]);
                h[r][1] = fma2(z2.y, c1, h[r][1]);
                h[r][2] = fma2(z2.y, c2_, h[r][2]);
                h[r][3] = fma2(z2.y, c3, h[r][3]);
            }
        }

        // ---- tanh + stage t (regs discarded after store) ----
        #pragma unroll
        for (int r = 0; r < RPW; ++r)
            #pragma unroll
            for (int j = 0; j < 4; ++j) {
                F2U hv; hv.u = h[r][j];
                F2U tv;
                tv.f.x = tanhfast(hv.f.x);
                tv.f.y = tanhfast(hv.f.y);
                *(ull*)&tw[r * HIDD + 64 * j + m2] = tv.u;
            }
        __syncwarp();

        // ---- GEMV2: x_next = x + 0.1 * t @ W2 ----
        ull acc[RPW][2];
        #pragma unroll
        for (int r = 0; r < RPW; ++r) { acc[r][0] = 0ull; acc[r][1] = 0ull; }
        #pragma unroll 4
        for (int q = 0; q < HIDD / 4; ++q) {
            ulonglong2 wa = w2a[q];
            ulonglong2 wb = w2b[q];
            #pragma unroll
            for (int r = 0; r < RPW; ++r) {
                ulonglong2 tv = *(const ulonglong2*)&tw[r * HIDD + 4 * q];
                acc[r][0] = fma2(tv.x, wa.x, acc[r][0]);
                acc[r][0] = fma2(tv.y, wa.y, acc[r][0]);
                acc[r][1] = fma2(tv.x, wb.x, acc[r][1]);
                acc[r][1] = fma2(tv.y, wb.y, acc[r][1]);
            }
        }
        #pragma unroll
        for (int r = 0; r < RPW; ++r) {
            int b = b0 + r;
            F2U a0; a0.u = acc[r][0];
            F2U a1; a1.u = acc[r][1];
            float xn0 = zd[r * ZD + lane].x      + 0.1f * (a0.f.x + a0.f.y);
            float xn1 = zd[r * ZD + 32 + lane].x + 0.1f * (a1.f.x + a1.f.y);
            size_t base_t = (size_t)b * (HH + 1) * NXD + (size_t)(k + 1) * NXD;
            size_t base_p = (size_t)b * HH * NXD + (size_t)k * NXD;
            out_xtraj[base_t + lane]      = xn0;
            out_xtraj[base_t + 32 + lane] = xn1;
            out_xpred[base_p + lane]      = xn0;
            out_xpred[base_p + 32 + lane] = xn1;
            zd[r * ZD + lane]      = make_float2(xn0, xn0);
            zd[r * ZD + 32 + lane] = make_float2(xn1, xn1);
        }

        // ---- gh = c2 * (1 - t^2): reload own t slots, overwrite in place ----
        __syncwarp();  // all lanes done broadcast-reading t
        #pragma unroll
        for (int r = 0; r < RPW; ++r)
            #pragma unroll
            for (int j = 0; j < 4; ++j) {
                ull tv = *(const ull*)&tw[r * HIDD + 64 * j + m2];
                ull gh = fma2(mul2(tv, tv), nc2p[j], c2p[j]);
                *(ull*)&tw[r * HIDD + 64 * j + m2] = gh;
            }
        __syncwarp();

        // ---- grad: g[i] = sum_m gh[m]*W1[i,m] ----
        // gx rows: all 8 rows per lane (i=lane, 32+lane).
        // gu rows split: lanes 0-15 rows 0-3, lanes 16-31 rows 4-7 (no dup work).
        ull ga[RPW], gb[RPW], gc4[4];
        #pragma unroll
        for (int r = 0; r < RPW; ++r) { ga[r] = 0ull; gb[r] = 0ull; }
        #pragma unroll
        for (int r = 0; r < 4; ++r) gc4[r] = 0ull;

        #pragma unroll 4
        for (int q = 0; q < HIDD / 4; ++q) {
            ulonglong2 wa = wia[q];
            ulonglong2 wb = wib[q];
            ulonglong2 wc = wic[q];
            ull gl[RPW][2];
            #pragma unroll
            for (int r = 0; r < RPW; ++r) {
                ulonglong2 gv = *(const ulonglong2*)&tw[r * HIDD + 4 * q];
                gl[r][0] = gv.x; gl[r][1] = gv.y;
                ga[r] = fma2(gv.x, wa.x, ga[r]);
                ga[r] = fma2(gv.y, wa.y, ga[r]);
                gb[r] = fma2(gv.x, wb.x, gb[r]);
                gb[r] = fma2(gv.y, wb.y, gb[r]);
            }
            #pragma unroll
            for (int r = 0; r < 4; ++r) {
                ull s0 = lo ? gl[r][0] : gl[r + 4][0];
                ull s1 = lo ? gl[r][1] : gl[r + 4][1];
                gc4[r] = fma2(s0, wc.x, gc4[r]);
                gc4[r] = fma2(s1, wc.y, gc4[r]);
            }
        }
        #pragma unroll
        for (int r = 0; r < RPW; ++r) {
            int b = b0 + r;
            F2U va; va.u = ga[r];
            F2U vb; vb.u = gb[r];
            size_t base_gx = (size_t)b * HH * NXD + (size_t)k * NXD;
            out_gx[base_gx + lane]      = 1.f + va.f.x + va.f.y;
            out_gx[base_gx + 32 + lane] = 1.f + vb.f.x + vb.f.y;
        }
        #pragma unroll
        for (int r = 0; r < 4; ++r) {
            int b = b0 + r + (lo ? 0 : 4);
            F2U vc; vc.u = gc4[r];
            out_gu[(size_t)b * HH * NUD + (size_t)k * NUD + ui] =
                vc.f.x + vc.f.y;
        }
        __syncwarp();  // protect tw/zd reuse next step
    }
}

// ---------------------------------------------------------------------------
extern "C" void kernel_launch(void* const* d_in, const int* in_sizes, int n_in,
                              void* d_out, int out_size) {
    const float* x0    = (const float*)d_in[0];
    const float* W1    = (const float*)d_in[2];
    const float* b1    = (const float*)d_in[3];
    const float* W2    = (const float*)d_in[4];
    const float* noise = (const float*)d_in[5];
    const int*   nit   = (const int*)d_in[6];

    float* out = (float*)d_out;
    float* out_u     = out + OFF_U;
    float* out_xtraj = out + OFF_XTRAJ;
    float* out_xpred = out + OFF_XPRED;
    float* out_gx    = out + OFF_GX;
    float* out_gu    = out + OFF_GU;

    {
        int tot = BB * HH * NUD;
        prep_kernel<<<(tot + 255) / 256, 256>>>(noise, nit, out_u);
    }

    const size_t smem_bytes =
        (size_t)(ZD * W1STRIDE + NXD * W2STRIDE + HIDD + HIDD) * sizeof(float)
        + (size_t)(NWARP * RPW * ZD) * sizeof(float2)
        + (size_t)(NWARP * RPW * HIDD) * sizeof(float);   // 205,056 B
    cudaFuncSetAttribute(mpc_kernel,
                         cudaFuncAttributeMaxDynamicSharedMemorySize,
                         (int)smem_bytes);
    mpc_kernel<<<BB / 32, 128, smem_bytes>>>(x0, W1, b1, W2,
                                             out_xtraj, out_xpred,
                                             out_gx, out_gu);
}

// round 10
// speedup vs baseline: 1.0684x; 1.0684x over previous
#include <cuda_runtime.h>
#include <cstddef>

// Problem constants
#define BB    4096
#define NXD   64
#define NUD   16
#define HH    50
#define HIDD  256
#define ZD    80
#define W1STRIDE 260
#define W2STRIDE 260

// Output layout
#define OFF_U      0
#define OFF_XTRAJ  (BB*NUD)
#define OFF_XPRED  (OFF_XTRAJ + BB*(HH+1)*NXD)
#define OFF_GX     (OFF_XPRED + BB*HH*NXD)
#define OFF_GU     (OFF_GX + BB*HH*NXD)

// smem layout (float offsets). Total 57,920 floats = 231,680 B (< 227 KB limit)
#define SM_W1    0                       // [80][260]
#define SM_W2T   (SM_W1 + ZD*W1STRIDE)   // [64][260]
#define SM_XD    (SM_W2T + NXD*W2STRIDE) // float2 [32 rows][64]
#define SM_TALL  (SM_XD + 32*64*2)       // float  [32 rows][256] t (u staging aliased per-warp)
#define SM_GALL  (SM_TALL + 32*256)      // float  [32 rows][256] gh fp32, SINGLE buffer
#define SM_TOTAL_F (SM_GALL + 32*256)

typedef unsigned long long ull;

__device__ float g_u9[BB * HH * NUD];

union F2U { ull u; float2 f; };

__device__ __forceinline__ ull fma2(ull a, ull b, ull c) {
    ull d;
    asm("fma.rn.f32x2 %0, %1, %2, %3;" : "=l"(d) : "l"(a), "l"(b), "l"(c));
    return d;
}
__device__ __forceinline__ ull mul2(ull a, ull b) {
    ull d;
    asm("mul.rn.f32x2 %0, %1, %2;" : "=l"(d) : "l"(a), "l"(b));
    return d;
}
// tanh(x) = 1 - 2/(exp2(2*log2e*x)+1)
__device__ __forceinline__ float tanhfast(float x) {
    float e, r;
    asm("ex2.approx.f32 %0, %1;" : "=f"(e) : "f"(x * 2.885390081777927f));
    asm("rcp.approx.f32 %0, %1;" : "=f"(r) : "f"(e + 1.0f));
    return fmaf(-2.0f, r, 1.0f);
}

// ---------------------------------------------------------------------------
__global__ void prep_kernel(const float* __restrict__ noise,
                            const int* __restrict__ nit_p,
                            float* __restrict__ out_u) {
    const int TOT = BB * HH * NUD;
    int idx = blockIdx.x * blockDim.x + threadIdx.x;
    if (idx >= TOT) return;
    int nit = *nit_p;
    float s = 0.f;
    for (int it = 0; it < nit - 1; ++it)
        s += noise[(size_t)it * TOT + idx];
    float u9 = 0.001f * s;
    g_u9[idx] = u9;
    int rem = idx % (HH * NUD);
    if (rem < NUD) {
        float u10 = u9 + 0.001f * noise[(size_t)(nit - 1) * TOT + idx];
        int b = idx / (HH * NUD);
        out_u[b * NUD + rem] = u10;
    }
}

// ---------------------------------------------------------------------------
// grid 128 x 256 threads. Warps 0-3: rollout (8 rows each). Warps 4-7: grad
// for the same rows, consuming the just-written fp32 gh (2 barriers/step).
// ---------------------------------------------------------------------------
__global__ __launch_bounds__(256, 1)
void mpc_kernel(const float* __restrict__ x0,
                const float* __restrict__ W1g,   // [80,256]
                const float* __restrict__ b1g,   // [256]
                const float* __restrict__ W2g,   // [256,64]
                float* __restrict__ out_xtraj,
                float* __restrict__ out_xpred,
                float* __restrict__ out_gx,
                float* __restrict__ out_gu) {
    extern __shared__ float smem[];
    float*  W1s  = smem + SM_W1;
    float*  W2Ts = smem + SM_W2T;
    float2* xd   = (float2*)(smem + SM_XD);
    float*  tall = smem + SM_TALL;
    float*  gall = smem + SM_GALL;

    const int tid = threadIdx.x;

    // ---- Stage weights + c2 scratch (parked in tall[0..255]) ----
    for (int idx = tid; idx < ZD * HIDD; idx += 256) {
        int i = idx >> 8, m = idx & 255;
        W1s[i * W1STRIDE + m] = W1g[idx];
    }
    for (int idx = tid; idx < HIDD * NXD; idx += 256) {
        int m = idx >> 6, j = idx & 63;
        W2Ts[j * W2STRIDE + m] = W2g[idx];
    }
    {
        int m = tid;
        float s = 0.f;
        #pragma unroll 8
        for (int j = 0; j < NXD; ++j) s += W2g[m * NXD + j];
        tall[m] = 0.1f * s;   // c2 scratch
    }
    __syncthreads();

    const int  w    = tid >> 5, lane = tid & 31;
    const int  wl   = w & 3;
    const bool roll = (w < 4);
    const int  lr   = wl * 8;
    const int  b0   = blockIdx.x * 32 + lr;
    const int  m2   = 2 * lane;
    const int  urh  = lane >> 4, ui = lane & 15;
    const bool lo16 = (lane < 16);

    ull b1p[4], c2p[4], nc2p[4];
    float up[4];
    if (roll) {
        #pragma unroll
        for (int j = 0; j < 4; ++j) {
            b1p[j] = *(const ull*)&b1g[64 * j + m2];
            F2U c; c.u = *(const ull*)&tall[64 * j + m2];
            c2p[j] = c.u;
            F2U n; n.f.x = -c.f.x; n.f.y = -c.f.y;
            nc2p[j] = n.u;
        }
        #pragma unroll
        for (int r = 0; r < 8; ++r) {
            int b = b0 + r;
            float xa = x0[b * NXD + lane];
            float xb = x0[b * NXD + 32 + lane];
            xd[(lr + r) * 64 + lane]      = make_float2(xa, xa);
            xd[(lr + r) * 64 + 32 + lane] = make_float2(xb, xb);
            size_t base = (size_t)b * (HH + 1) * NXD;
            out_xtraj[base + lane]      = xa;
            out_xtraj[base + 32 + lane] = xb;
        }
        #pragma unroll
        for (int v = 0; v < 4; ++v)
            up[v] = g_u9[(size_t)(b0 + 2 * v + urh) * HH * NUD + ui];
    }
    __syncthreads();   // c2 scratch consumed; tall free

    if (roll) {
        // u staging aliases THIS warp's own tall row block (dead between steps)
        float2* ud = (float2*)(tall + lr * 256);   // [8 rows][16] float2
        const ulonglong2* w2a = (const ulonglong2*)&W2Ts[lane * W2STRIDE];
        const ulonglong2* w2b = (const ulonglong2*)&W2Ts[(lane + 32) * W2STRIDE];

        for (int k = 0; k < HH; ++k) {
            // ---- stage controls (dup) ----
            #pragma unroll
            for (int v = 0; v < 4; ++v)
                ud[(2 * v + urh) * 16 + ui] = make_float2(up[v], up[v]);
            __syncwarp();
            if (k + 1 < HH) {
                #pragma unroll
                for (int v = 0; v < 4; ++v)
                    up[v] = g_u9[(size_t)(b0 + 2 * v + urh) * HH * NUD
                                 + (k + 1) * NUD + ui];
            }

            // ---- GEMV1: h = z @ W1 + b1 ----
            ull h[8][4];
            #pragma unroll
            for (int r = 0; r < 8; ++r)
                #pragma unroll
                for (int j = 0; j < 4; ++j) h[r][j] = b1p[j];

            #pragma unroll 2
            for (int i = 0; i < NXD; i += 2) {       // x part
                const float* wr0 = &W1s[i * W1STRIDE];
                const float* wr1 = &W1s[(i + 1) * W1STRIDE];
                ull a0 = *(const ull*)&wr0[m2];
                ull a1 = *(const ull*)&wr0[m2 + 64];
                ull a2 = *(const ull*)&wr0[m2 + 128];
                ull a3 = *(const ull*)&wr0[m2 + 192];
                ull c0 = *(const ull*)&wr1[m2];
                ull c1 = *(const ull*)&wr1[m2 + 64];
                ull c2_ = *(const ull*)&wr1[m2 + 128];
                ull c3 = *(const ull*)&wr1[m2 + 192];
                #pragma unroll
                for (int r = 0; r < 8; ++r) {
                    ulonglong2 z2 = *(const ulonglong2*)&xd[(lr + r) * 64 + i];
                    h[r][0] = fma2(z2.x, a0, h[r][0]);
                    h[r][1] = fma2(z2.x, a1, h[r][1]);
                    h[r][2] = fma2(z2.x, a2, h[r][2]);
                    h[r][3] = fma2(z2.x, a3, h[r][3]);
                    h[r][0] = fma2(z2.y, c0, h[r][0]);
                    h[r][1] = fma2(z2.y, c1, h[r][1]);
                    h[r][2] = fma2(z2.y, c2_, h[r][2]);
                    h[r][3] = fma2(z2.y, c3, h[r][3]);
                }
            }
            #pragma unroll 2
            for (int i = NXD; i < ZD; i += 2) {      // u part
                const float* wr0 = &W1s[i * W1STRIDE];
                const float* wr1 = &W1s[(i + 1) * W1STRIDE];
                ull a0 = *(const ull*)&wr0[m2];
                ull a1 = *(const ull*)&wr0[m2 + 64];
                ull a2 = *(const ull*)&wr0[m2 + 128];
                ull a3 = *(const ull*)&wr0[m2 + 192];
                ull c0 = *(const ull*)&wr1[m2];
                ull c1 = *(const ull*)&wr1[m2 + 64];
                ull c2_ = *(const ull*)&wr1[m2 + 128];
                ull c3 = *(const ull*)&wr1[m2 + 192];
                #pragma unroll
                for (int r = 0; r < 8; ++r) {
                    ulonglong2 z2 = *(const ulonglong2*)&ud[r * 16 + (i - NXD)];
                    h[r][0] = fma2(z2.x, a0, h[r][0]);
                    h[r][1] = fma2(z2.x, a1, h[r][1]);
                    h[r][2] = fma2(z2.x, a2, h[r][2]);
                    h[r][3] = fma2(z2.x, a3, h[r][3]);
                    h[r][0] = fma2(z2.y, c0, h[r][0]);
                    h[r][1] = fma2(z2.y, c1, h[r][1]);
                    h[r][2] = fma2(z2.y, c2_, h[r][2]);
                    h[r][3] = fma2(z2.y, c3, h[r][3]);
                }
            }

            __syncthreads();   // A: grad finished reading gh(k-1)

            // ---- tanh; stage t (f32) and gh (f32) ----
            #pragma unroll
            for (int r = 0; r < 8; ++r)
                #pragma unroll
                for (int j = 0; j < 4; ++j) {
                    F2U hv; hv.u = h[r][j];
                    F2U tv;
                    tv.f.x = tanhfast(hv.f.x);
                    tv.f.y = tanhfast(hv.f.y);
                    *(ull*)&tall[(lr + r) * 256 + 64 * j + m2] = tv.u;
                    ull gh = fma2(mul2(tv.u, tv.u), nc2p[j], c2p[j]);
                    *(ull*)&gall[(lr + r) * 256 + 64 * j + m2] = gh;
                }

            __syncthreads();   // B: gh(k) ready

            // ---- GEMV2: x_next = x + 0.1 * t @ W2 ----
            ull acc[8][2];
            #pragma unroll
            for (int r = 0; r < 8; ++r) { acc[r][0] = 0ull; acc[r][1] = 0ull; }
            #pragma unroll 4
            for (int q = 0; q < HIDD / 4; ++q) {
                ulonglong2 wa = w2a[q];
                ulonglong2 wb = w2b[q];
                #pragma unroll
                for (int r = 0; r < 8; ++r) {
                    ulonglong2 tv =
                        *(const ulonglong2*)&tall[(lr + r) * 256 + 4 * q];
                    acc[r][0] = fma2(tv.x, wa.x, acc[r][0]);
                    acc[r][0] = fma2(tv.y, wa.y, acc[r][0]);
                    acc[r][1] = fma2(tv.x, wb.x, acc[r][1]);
                    acc[r][1] = fma2(tv.y, wb.y, acc[r][1]);
                }
            }
            #pragma unroll
            for (int r = 0; r < 8; ++r) {
                int b = b0 + r;
                F2U a0; a0.u = acc[r][0];
                F2U a1; a1.u = acc[r][1];
                float xn0 = xd[(lr + r) * 64 + lane].x
                            + 0.1f * (a0.f.x + a0.f.y);
                float xn1 = xd[(lr + r) * 64 + 32 + lane].x
                            + 0.1f * (a1.f.x + a1.f.y);
                size_t base_t = (size_t)b * (HH + 1) * NXD
                                + (size_t)(k + 1) * NXD;
                size_t base_p = (size_t)b * HH * NXD + (size_t)k * NXD;
                out_xtraj[base_t + lane]      = xn0;
                out_xtraj[base_t + 32 + lane] = xn1;
                out_xpred[base_p + lane]      = xn0;
                out_xpred[base_p + 32 + lane] = xn1;
                xd[(lr + r) * 64 + lane]      = make_float2(xn0, xn0);
                xd[(lr + r) * 64 + 32 + lane] = make_float2(xn1, xn1);
            }
            __syncwarp();
        }
    } else {
        // ---------------- grad warps ----------------
        const ulonglong2* wia = (const ulonglong2*)&W1s[lane * W1STRIDE];
        const ulonglong2* wib = (const ulonglong2*)&W1s[(32 + lane) * W1STRIDE];
        const ulonglong2* wic = (const ulonglong2*)&W1s[(64 + ui) * W1STRIDE];
        const float* gb_ = gall + lr * 256;

        for (int k = 0; k < HH; ++k) {
            __syncthreads();   // A
            __syncthreads();   // B: gh(k) ready

            ull ga[8], gb[8], gc4[4];
            #pragma unroll
            for (int r = 0; r < 8; ++r) { ga[r] = 0ull; gb[r] = 0ull; }
            #pragma unroll
            for (int r = 0; r < 4; ++r) gc4[r] = 0ull;

            #pragma unroll 4
            for (int q = 0; q < HIDD / 4; ++q) {
                ulonglong2 wa = wia[q];
                ulonglong2 wb = wib[q];
                ulonglong2 wc = wic[q];
                ull gl[8][2];
                #pragma unroll
                for (int r = 0; r < 8; ++r) {
                    ulonglong2 gv = *(const ulonglong2*)&gb_[r * 256 + 4 * q];
                    gl[r][0] = gv.x; gl[r][1] = gv.y;
                    ga[r] = fma2(gv.x, wa.x, ga[r]);
                    ga[r] = fma2(gv.y, wa.y, ga[r]);
                    gb[r] = fma2(gv.x, wb.x, gb[r]);
                    gb[r] = fma2(gv.y, wb.y, gb[r]);
                }
                #pragma unroll
                for (int r = 0; r < 4; ++r) {
                    ull s0 = lo16 ? gl[r][0] : gl[r + 4][0];
                    ull s1 = lo16 ? gl[r][1] : gl[r + 4][1];
                    gc4[r] = fma2(s0, wc.x, gc4[r]);
                    gc4[r] = fma2(s1, wc.y, gc4[r]);
                }
            }
            #pragma unroll
            for (int r = 0; r < 8; ++r) {
                int b = b0 + r;
                F2U va; va.u = ga[r];
                F2U vb; vb.u = gb[r];
                size_t base_gx = (size_t)b * HH * NXD + (size_t)k * NXD;
                out_gx[base_gx + lane]      = 1.f + va.f.x + va.f.y;
                out_gx[base_gx + 32 + lane] = 1.f + vb.f.x + vb.f.y;
            }
            #pragma unroll
            for (int r = 0; r < 4; ++r) {
                int b = b0 + r + (lo16 ? 0 : 4);
                F2U vc; vc.u = gc4[r];
                out_gu[(size_t)b * HH * NUD + (size_t)k * NUD + ui] =
                    vc.f.x + vc.f.y;
            }
        }
    }
}

// ---------------------------------------------------------------------------
extern "C" void kernel_launch(void* const* d_in, const int* in_sizes, int n_in,
                              void* d_out, int out_size) {
    const float* x0    = (const float*)d_in[0];
    const float* W1    = (const float*)d_in[2];
    const float* b1    = (const float*)d_in[3];
    const float* W2    = (const float*)d_in[4];
    const float* noise = (const float*)d_in[5];
    const int*   nit   = (const int*)d_in[6];

    float* out = (float*)d_out;
    float* out_u     = out + OFF_U;
    float* out_xtraj = out + OFF_XTRAJ;
    float* out_xpred = out + OFF_XPRED;
    float* out_gx    = out + OFF_GX;
    float* out_gu    = out + OFF_GU;

    {
        int tot = BB * HH * NUD;
        prep_kernel<<<(tot + 255) / 256, 256>>>(noise, nit, out_u);
    }

    const size_t smem_bytes = (size_t)SM_TOTAL_F * sizeof(float);  // 231,680
    cudaFuncSetAttribute(mpc_kernel,
                         cudaFuncAttributeMaxDynamicSharedMemorySize,
                         (int)smem_bytes);
    mpc_kernel<<<BB / 32, 256, smem_bytes>>>(x0, W1, b1, W2,
                                             out_xtraj, out_xpred,
                                             out_gx, out_gu);
}